// round 3
// baseline (speedup 1.0000x reference)
#include <cuda_runtime.h>

// Multi-scale SSIM quadtree loss, N=256, levels d=8..0.
// Level d: block side h=256>>d, mu = block_sum/h (faithful reference bug),
// weight W[d] = K_LOSS[d]*0.25^d, K_LOSS={9,8,7,6,5,4,3,2,1}.
//
// 64 CTAs x 512 threads. CTA = 32x32 tile (16 warps as 4x4 grid of 8x8
// blocks). All reductions are warp-shuffle quadtrees in registers; each
// replicated block term is added with weight/replication (exact pow2).
// One __syncthreads per CTA; warps 1..15 exit after it. Warp 0 folds d=4,
// d=3, takes the atomic ticket (shfl-broadcast), and — if last — does the
// entire 8x8 tile-grid phase B (d=2..0) with zero barriers.

#define SSIM_C1 0.2f

__device__ float g_Sx[64];
__device__ float g_Sy[64];
__device__ float g_partial[64];
__device__ unsigned int g_count = 0;

// Weights pre-divided by lane replication (all exact in fp32):
#define W8_R 1.52587890625e-05f   // 1/65536          d=8 rep1
#define W7_R 6.103515625e-05f     // (2/16384)/2      d=7 rep2
#define W6_R 9.1552734375e-05f    // (3/4096)/8       d=6 rep8
#define W5_R 1.220703125e-04f     // (4/1024)/32      d=5 rep32
#define W4_R 0.0048828125f        // (5/256)/4        d=4 rep4
#define W3_R 0.005859375f         // (6/64)/16        d=3 rep16
#define W2_R 0.21875f             // (7/16)/2         d=2 rep2
#define W1_R 0.25f                // (8/4)/8          d=1 rep8
#define W0_R 0.28125f             // 9/32             d=0 rep32

__device__ __forceinline__ float loss_term(float sx, float sy, float invh) {
    float mx = sx * invh;
    float my = sy * invh;
    return 1.0f - (2.0f * mx * my + SSIM_C1) / (mx * mx + my * my + SSIM_C1);
}

// Quadtree over an 8x8 grid of per-lane 1x2 sums (lane l -> row l>>2,
// colpair l&3). Adds 3 level terms, returns full 8x8-grid sums.
__device__ __forceinline__ void warp_quadtree(
    float s1x, float s1y, float& acc, float& s8x, float& s8y,
    float wA, float ihA, float wB, float ihB, float wC, float ihC)
{
    float s2x = s1x + __shfl_xor_sync(0xffffffffu, s1x, 4);
    float s2y = s1y + __shfl_xor_sync(0xffffffffu, s1y, 4);
    acc += wA * loss_term(s2x, s2y, ihA);
    float s4x = s2x + __shfl_xor_sync(0xffffffffu, s2x, 8);
    float s4y = s2y + __shfl_xor_sync(0xffffffffu, s2y, 8);
    s4x += __shfl_xor_sync(0xffffffffu, s4x, 1);
    s4y += __shfl_xor_sync(0xffffffffu, s4y, 1);
    acc += wB * loss_term(s4x, s4y, ihB);
    s8x = s4x + __shfl_xor_sync(0xffffffffu, s4x, 16);
    s8y = s4y + __shfl_xor_sync(0xffffffffu, s4y, 16);
    s8x += __shfl_xor_sync(0xffffffffu, s8x, 2);
    s8y += __shfl_xor_sync(0xffffffffu, s8y, 2);
    acc += wC * loss_term(s8x, s8y, ihC);
}

__device__ __forceinline__ float warp_sum(float v) {
    v += __shfl_xor_sync(0xffffffffu, v, 16);
    v += __shfl_xor_sync(0xffffffffu, v, 8);
    v += __shfl_xor_sync(0xffffffffu, v, 4);
    v += __shfl_xor_sync(0xffffffffu, v, 2);
    v += __shfl_xor_sync(0xffffffffu, v, 1);
    return v;
}

__global__ void __launch_bounds__(512) Loss_13967233646850_kernel(
    const float* __restrict__ x, const float* __restrict__ y,
    float* __restrict__ out)
{
    __shared__ float sSx[16], sSy[16], sAcc[16];

    const int tid  = threadIdx.x;
    const int lane = tid & 31;
    const int w    = tid >> 5;           // warp 0..15 -> 4x4 grid of 8x8 blocks
    const int b    = blockIdx.x;         // 64 CTAs -> 8x8 grid of 32x32 tiles

    // ---- Phase A (per warp): d=8..5 over this warp's 8x8 pixel block ----
    {
        const int row = (b >> 3) * 32 + (w >> 2) * 8 + (lane >> 2);
        const int col = (b & 7)  * 32 + (w & 3)  * 8 + (lane & 3) * 2;
        const int idx = row * 256 + col;

        const float2 px = *(const float2*)(x + idx);
        const float2 py = *(const float2*)(y + idx);

        float acc = W8_R * (loss_term(px.x, py.x, 1.0f) +
                            loss_term(px.y, py.y, 1.0f));
        float s8x, s8y;
        warp_quadtree(px.x + px.y, py.x + py.y, acc, s8x, s8y,
                      W7_R, 0.5f, W6_R, 0.25f, W5_R, 0.125f);
        acc = warp_sum(acc);
        if (lane == 0) { sSx[w] = s8x; sSy[w] = s8y; sAcc[w] = acc; }
    }
    __syncthreads();
    if (w != 0) return;

    // ---- Warp 0: fold 4x4 warp grid (d=4, d=3), write tile sums, ticket ----
    unsigned int ticket;
    {
        // lane<16 holds warp sums (lane = warp idx: r=lane>>2, c=lane&3);
        // lanes 16..31 carry zeros: loss_term(0,0)==0, so their replicated
        // block terms vanish and they never mix with lanes 0..15 under
        // masks {1,2,4,8}.
        float sx = (lane < 16) ? sSx[lane]  : 0.0f;
        float sy = (lane < 16) ? sSy[lane]  : 0.0f;
        float acc = (lane < 16) ? sAcc[lane] : 0.0f;

        // d=4: 16x16 block = 2x2 warp blocks (xor 4 = r bit0, xor 1 = c bit0)
        float s16x = sx + __shfl_xor_sync(0xffffffffu, sx, 4);
        float s16y = sy + __shfl_xor_sync(0xffffffffu, sy, 4);
        s16x += __shfl_xor_sync(0xffffffffu, s16x, 1);
        s16y += __shfl_xor_sync(0xffffffffu, s16y, 1);
        acc += W4_R * loss_term(s16x, s16y, 1.0f / 16.0f);
        // d=3: 32x32 tile (xor 8 = r bit1, xor 2 = c bit1)
        float s32x = s16x + __shfl_xor_sync(0xffffffffu, s16x, 8);
        float s32y = s16y + __shfl_xor_sync(0xffffffffu, s16y, 8);
        s32x += __shfl_xor_sync(0xffffffffu, s32x, 2);
        s32y += __shfl_xor_sync(0xffffffffu, s32y, 2);
        acc += W3_R * loss_term(s32x, s32y, 1.0f / 32.0f);

        acc = warp_sum(acc);
        if (lane == 0) {
            g_Sx[b] = s32x; g_Sy[b] = s32y; g_partial[b] = acc;
            __threadfence();
            ticket = atomicAdd(&g_count, 1u);
        }
        ticket = __shfl_sync(0xffffffffu, ticket, 0);
    }
    if (ticket != gridDim.x - 1) return;

    // ---- Phase B (warp 0 of last CTA): 8x8 tile grid, d=2..0, no barriers ----
    __threadfence();
    {
        const int ti = (lane >> 2) * 8 + (lane & 3) * 2;   // 1x2 tile pair
        const float2 tx = *(const float2*)(g_Sx + ti);
        const float2 ty = *(const float2*)(g_Sy + ti);
        const float2 tp = *(const float2*)(g_partial + ti);

        float acc = tp.x + tp.y;
        float sx, sy;
        warp_quadtree(tx.x + tx.y, ty.x + ty.y, acc, sx, sy,
                      W2_R, 1.0f / 64.0f, W1_R, 1.0f / 128.0f, W0_R, 1.0f / 256.0f);
        acc = warp_sum(acc);
        if (lane == 0) {
            out[0] = acc;
            g_count = 0;   // reset for graph replay
        }
    }
}

extern "C" void kernel_launch(void* const* d_in, const int* in_sizes, int n_in,
                              void* d_out, int out_size) {
    const float* x = (const float*)d_in[0];
    const float* y = (const float*)d_in[1];
    float* out = (float*)d_out;
    Loss_13967233646850_kernel<<<64, 512>>>(x, y, out);
}

// round 4
// speedup vs baseline: 1.0074x; 1.0074x over previous
#include <cuda_runtime.h>

// Multi-scale SSIM quadtree loss, N=256, levels d=8..0.
// Level d: block side h=256>>d, mu = block_sum/h (faithful reference bug),
// weight W[d] = K_LOSS[d]*0.25^d, K_LOSS={9,8,7,6,5,4,3,2,1}.
//
// 64 CTAs x 256 threads (8 warps). CTA = 32x32 tile; warp = 8x16 block;
// lane = 1x4 pixel strip (one float4 per image). All reductions are
// warp-shuffle quadtrees; replicated block terms use weight/replication
// (exact pow2). Producers bar.arrive and retire; warp 0 bar.syncs, folds
// d=4/d=3, writes one float4 tile record, takes the atomic ticket; the
// last CTA's warp 0 finishes the 8x8 tile grid (d=2..0), zero barriers.

#define SSIM_C1 0.2f

__device__ float4 g_tile[64];          // (Sx, Sy, partial, 0) per 32x32 tile
__device__ unsigned int g_count = 0;

// Weights pre-divided by replication factor (all exact in fp32):
#define W8_1  1.52587890625e-05f   // 1/65536            d=8
#define W7_2  6.103515625e-05f     // (2/16384)/2        d=7 rep2
#define W6_4  1.8310546875e-04f    // (3/4096)/4         d=6 rep4
#define W5_16 2.44140625e-04f      // (4/1024)/16        d=5 rep16
#define W4_2  0.009765625f         // (5/256)/2          d=4 rep2
#define W3_8  0.01171875f          // (6/64)/8           d=3 rep8
#define W2_2  0.21875f             // (7/16)/2           d=2 rep2
#define W1_8  0.25f                // (8/4)/8            d=1 rep8
#define W0_32 0.28125f             // 9/32               d=0 rep32

__device__ __forceinline__ float loss_term(float sx, float sy, float invh) {
    float mx = sx * invh;
    float my = sy * invh;
    return 1.0f - (2.0f * mx * my + SSIM_C1) / (mx * mx + my * my + SSIM_C1);
}

__device__ __forceinline__ float warp_sum(float v) {
    v += __shfl_xor_sync(0xffffffffu, v, 16);
    v += __shfl_xor_sync(0xffffffffu, v, 8);
    v += __shfl_xor_sync(0xffffffffu, v, 4);
    v += __shfl_xor_sync(0xffffffffu, v, 2);
    v += __shfl_xor_sync(0xffffffffu, v, 1);
    return v;
}

// Quadtree over an 8x8 grid of per-lane 1x2 sums (lane l -> row l>>2,
// colpair l&3). Adds 3 level terms (reps 2/8/32), returns 8x8-grid sums.
__device__ __forceinline__ void grid8_quadtree(
    float s1x, float s1y, float& acc, float& s8x, float& s8y,
    float wA, float ihA, float wB, float ihB, float wC, float ihC)
{
    float s2x = s1x + __shfl_xor_sync(0xffffffffu, s1x, 4);
    float s2y = s1y + __shfl_xor_sync(0xffffffffu, s1y, 4);
    acc += wA * loss_term(s2x, s2y, ihA);
    float s4x = s2x + __shfl_xor_sync(0xffffffffu, s2x, 8);
    float s4y = s2y + __shfl_xor_sync(0xffffffffu, s2y, 8);
    s4x += __shfl_xor_sync(0xffffffffu, s4x, 1);
    s4y += __shfl_xor_sync(0xffffffffu, s4y, 1);
    acc += wB * loss_term(s4x, s4y, ihB);
    s8x = s4x + __shfl_xor_sync(0xffffffffu, s4x, 16);
    s8y = s4y + __shfl_xor_sync(0xffffffffu, s4y, 16);
    s8x += __shfl_xor_sync(0xffffffffu, s8x, 2);
    s8y += __shfl_xor_sync(0xffffffffu, s8y, 2);
    acc += wC * loss_term(s8x, s8y, ihC);
}

__global__ void __launch_bounds__(256) Loss_13967233646850_kernel(
    const float* __restrict__ x, const float* __restrict__ y,
    float* __restrict__ out)
{
    __shared__ float sSx[8], sSy[8], sAcc[8];

    const int tid  = threadIdx.x;
    const int lane = tid & 31;
    const int w    = tid >> 5;          // 8 warps: 4x2 grid of 8x16 blocks
    const int b    = blockIdx.x;        // 64 CTAs: 8x8 grid of 32x32 tiles

    // ---- Phase A (per warp): d=8..5 over this warp's 8x16 pixel block ----
    {
        // lane -> row lane>>2 (8 rows), col quad lane&3 (16 cols in 4-strips)
        const int row = (b >> 3) * 32 + (w >> 1) * 8 + (lane >> 2);
        const int col = (b & 7)  * 32 + (w & 1) * 16 + (lane & 3) * 4;
        const int idx = row * 256 + col;

        const float4 px = *(const float4*)(x + idx);
        const float4 py = *(const float4*)(y + idx);

        // d=8: per pixel
        float acc = W8_1 * (loss_term(px.x, py.x, 1.0f) + loss_term(px.y, py.y, 1.0f) +
                            loss_term(px.z, py.z, 1.0f) + loss_term(px.w, py.w, 1.0f));

        // 1x2 row sums within the strip
        float sabx = px.x + px.y, scdx = px.z + px.w;
        float saby = py.x + py.y, scdy = py.z + py.w;

        // d=7: 2x2 blocks (vertical pair via xor4); two per lane, rep2 each
        float s2Lx = sabx + __shfl_xor_sync(0xffffffffu, sabx, 4);
        float s2Ly = saby + __shfl_xor_sync(0xffffffffu, saby, 4);
        float s2Rx = scdx + __shfl_xor_sync(0xffffffffu, scdx, 4);
        float s2Ry = scdy + __shfl_xor_sync(0xffffffffu, scdy, 4);
        acc += W7_2 * (loss_term(s2Lx, s2Ly, 0.5f) + loss_term(s2Rx, s2Ry, 0.5f));

        // d=6: 4x4 (rows via xor8, cols = full strip), rep4
        float s4x = s2Lx + s2Rx, s4y = s2Ly + s2Ry;
        s4x += __shfl_xor_sync(0xffffffffu, s4x, 8);
        s4y += __shfl_xor_sync(0xffffffffu, s4y, 8);
        acc += W6_4 * loss_term(s4x, s4y, 0.25f);

        // d=5: 8x8 (rows via xor16, col quads via xor1), rep16
        float s8x = s4x + __shfl_xor_sync(0xffffffffu, s4x, 16);
        float s8y = s4y + __shfl_xor_sync(0xffffffffu, s4y, 16);
        s8x += __shfl_xor_sync(0xffffffffu, s8x, 1);
        s8y += __shfl_xor_sync(0xffffffffu, s8y, 1);
        acc += W5_16 * loss_term(s8x, s8y, 0.125f);

        // warp total 8x16 (col quads via xor2)
        float swx = s8x + __shfl_xor_sync(0xffffffffu, s8x, 2);
        float swy = s8y + __shfl_xor_sync(0xffffffffu, s8y, 2);

        acc = warp_sum(acc);
        if (lane == 0) { sSx[w] = swx; sSy[w] = swy; sAcc[w] = acc; }
    }

    // Producers signal and retire; warp 0 waits for all 8 warps.
    if (w != 0) {
        asm volatile("bar.arrive 1, 256;" ::: "memory");
        return;
    }
    asm volatile("bar.sync 1, 256;" ::: "memory");

    // ---- Warp 0: fold 8 warp blocks (d=4, d=3), write tile, ticket ----
    unsigned int ticket;
    {
        // lane<8 holds warp (wr=lane>>1, wc=lane&1) 8x16 sums; others zero
        // (loss_term(0,0)==0, and xor1/2/4 keep zero lanes among zeros).
        float sx  = (lane < 8) ? sSx[lane]  : 0.0f;
        float sy  = (lane < 8) ? sSy[lane]  : 0.0f;
        float acc = (lane < 8) ? sAcc[lane] : 0.0f;

        // d=4: 16x16 = vertical warp pair (wr bit0 = lane bit1 -> xor2), rep2
        float s16x = sx + __shfl_xor_sync(0xffffffffu, sx, 2);
        float s16y = sy + __shfl_xor_sync(0xffffffffu, sy, 2);
        acc += W4_2 * loss_term(s16x, s16y, 1.0f / 16.0f);

        // d=3: 32x32 tile (wr bit1 -> xor4, wc -> xor1), rep8
        float s32x = s16x + __shfl_xor_sync(0xffffffffu, s16x, 4);
        float s32y = s16y + __shfl_xor_sync(0xffffffffu, s16y, 4);
        s32x += __shfl_xor_sync(0xffffffffu, s32x, 1);
        s32y += __shfl_xor_sync(0xffffffffu, s32y, 1);
        acc += W3_8 * loss_term(s32x, s32y, 1.0f / 32.0f);

        acc = warp_sum(acc);
        if (lane == 0) {
            g_tile[b] = make_float4(s32x, s32y, acc, 0.0f);
            __threadfence();
            ticket = atomicAdd(&g_count, 1u);
        }
        ticket = __shfl_sync(0xffffffffu, ticket, 0);
    }
    if (ticket != gridDim.x - 1) return;

    // ---- Phase B (warp 0 of last CTA): 8x8 tile grid, d=2..0 ----
    __threadfence();
    {
        const int ti = (lane >> 2) * 8 + (lane & 3) * 2;   // 1x2 tile pair
        const float4 t0 = g_tile[ti];
        const float4 t1 = g_tile[ti + 1];

        float acc = t0.z + t1.z;
        float sx, sy;
        grid8_quadtree(t0.x + t1.x, t0.y + t1.y, acc, sx, sy,
                       W2_2, 1.0f / 64.0f, W1_8, 1.0f / 128.0f, W0_32, 1.0f / 256.0f);
        acc = warp_sum(acc);
        if (lane == 0) {
            out[0] = acc;
            g_count = 0;   // reset for graph replay
        }
    }
}

extern "C" void kernel_launch(void* const* d_in, const int* in_sizes, int n_in,
                              void* d_out, int out_size) {
    const float* x = (const float*)d_in[0];
    const float* y = (const float*)d_in[1];
    float* out = (float*)d_out;
    Loss_13967233646850_kernel<<<64, 256>>>(x, y, out);
}